// round 17
// baseline (speedup 1.0000x reference)
#include <cuda_runtime.h>
#include <cuda_fp16.h>
#include <cstdint>

#define NB 2048
#define NROWS (NB + 2)
#define TPB 256
#define GRID_FAST 740
#define GRID_TAIL 1184

__device__ double g_parts[2048];
__device__ unsigned int g_count = 0;
// fp16 LUT row = 64 half2 words (256B), SEGREGATED:
//   words [0:32)  = (P0,P1) values: word 4j+t  -> element m = 4j+t (lane j)
//   words [32:64) = slopes (next row - this row), same indexing
//   m <  8: P0 = ws[m]·GS,        P1 = ws[16+m]·GS·sqrt3   (g = S1)
//   m >= 8: u=(m-8)/3: P0 = ws[24+u]·GS, P1 = ws[8+u]·GS   (g = unit[(m-8)%3])
__device__ __align__(16) __half2 g_LUTh[NROWS * 64];

// ---------------------------------------------------------------------------
// prep: thread-per-row ws, staged in smem, packed segregated fp16. (R15)
// ---------------------------------------------------------------------------
__global__ void __launch_bounds__(TPB)
prep_kernel(const float* __restrict__ W1, const float* __restrict__ W2) {
    __shared__ float sW2r[512];
    __shared__ float sW1[160];
    __shared__ float sws[129][33];

    int tid = threadIdx.x;
    for (int q = tid; q < 512; q += TPB) {
        int c = q >> 5, o = q & 31;
        const float4* p = (const float4*)(W2 + c * 256 + o * 8);
        float4 u0 = __ldg(p), u1 = __ldg(p + 1);
        sW2r[q] = u0.x + u0.y + u0.z + u0.w + u1.x + u1.y + u1.z + u1.w;
    }
    for (int q = tid; q < 160; q += TPB) sW1[q] = W1[q];
    __syncthreads();

    int rbase = blockIdx.x * 128;
    if (tid <= 128) {
        int row = rbase + tid;
        float ws[32];
#pragma unroll
        for (int o = 0; o < 32; o++) ws[o] = 0.f;
        if (row < NB) {
            float r = row * (3.0f / NB);
            float f[10];
#pragma unroll
            for (int k = 0; k < 10; k++) {
                float c = (k + 1) * (3.0f / 11.0f);
                float d = (r - c) * (11.0f / 3.0f);
                float den = 1.0f - d * d;
                f[k] = (den > 0.f) ? 1.14136f * __expf(2.0f - 2.0f / den)
                                   : 0.f;
            }
            float h[16];
#pragma unroll
            for (int c = 0; c < 16; c++) {
                float s = 0.f;
#pragma unroll
                for (int k = 0; k < 10; k++) s += f[k] * sW1[k * 16 + c];
                h[c] = fmaxf(s, 0.f) * 1.4142135623730951f;
            }
#pragma unroll
            for (int c = 0; c < 16; c++)
#pragma unroll
                for (int o = 0; o < 32; o++) ws[o] += h[c] * sW2r[c * 32 + o];
        }
#pragma unroll
        for (int o = 0; o < 32; o++) sws[tid][o] = ws[o];
    }
    __syncthreads();

    const float GS = 0.015625f;
    const float GS3 = GS * 1.7320508075688772f;
    for (int item = tid; item < 128 * 32; item += TPB) {
        int rl = item >> 5, m = item & 31;
        int row = rbase + rl;
        if (row >= NROWS) continue;
        int o0, o1;
        float s1;
        if (m < 8) { o0 = m; o1 = 16 + m; s1 = GS3; }
        else { int u = (m - 8) / 3; o0 = 24 + u; o1 = 8 + u; s1 = GS; }
        float a0 = sws[rl][o0] * GS, a1 = sws[rl][o1] * s1;
        float b0 = sws[rl + 1][o0] * GS, b1 = sws[rl + 1][o1] * s1;
        g_LUTh[row * 64 + m] = __floats2half2_rn(a0, a1);
        g_LUTh[row * 64 + 32 + m] = __floats2half2_rn(b0 - a0, b1 - a1);
    }
}

// ---------------------------------------------------------------------------
// block reduce + last-block finish (shared by both edge kernels)
// ---------------------------------------------------------------------------
__device__ __forceinline__ void finish_reduce(float facc, float* out,
                                              int tid, int lane, int wid) {
    __shared__ double sredd[TPB / 32];
    __shared__ int sflag;
#pragma unroll
    for (int off = 16; off > 0; off >>= 1)
        facc += __shfl_down_sync(0xffffffffu, facc, off);
    if (lane == 0) sredd[wid] = (double)facc;
    __syncthreads();
    if (tid == 0) {
        double b = 0.0;
#pragma unroll
        for (int w = 0; w < TPB / 32; w++) b += sredd[w];
        g_parts[blockIdx.x] = b;
        __threadfence();
        unsigned int prev = atomicAdd(&g_count, 1u);
        sflag = (prev == gridDim.x - 1) ? 1 : 0;
    }
    __syncthreads();
    if (sflag) {
        __threadfence();
        double s = 0.0;
        for (int i = tid; i < (int)gridDim.x; i += TPB)
            s += ((volatile double*)g_parts)[i];
#pragma unroll
        for (int off = 16; off > 0; off >>= 1)
            s += __shfl_down_sync(0xffffffffu, s, off);
        __shared__ double fin[TPB / 32];
        if (lane == 0) fin[wid] = s;
        __syncthreads();
        if (tid == 0) {
            double v = 0.0;
#pragma unroll
            for (int w = 0; w < TPB / 32; w++) v += fin[w];
            out[0] = (float)v;
            g_count = 0;
        }
    }
}

// ---------------------------------------------------------------------------
// FAST edge kernel (E % 32 == 0): 3-stage software pipeline.
// iter i: [1] ev/idx loads for tile i+2; [2] scalar chain + LUT/feat loads
// for tile i+1 (ev landed one iter ago); [3] consume tile i (LUT landed one
// iter ago). No load is consumed in the iteration it was issued.
// ---------------------------------------------------------------------------
__global__ void __launch_bounds__(TPB, 5)
edge_fast(const float* __restrict__ feat, const float* __restrict__ evec,
          const int* __restrict__ esrc, float* __restrict__ out, int E) {
    int tid = threadIdx.x;
    int lane = tid & 31;
    int wid = tid >> 5;
    int grp = lane >> 3;
    int j = lane & 7;

    int i0 = (j + 1) % 3;
    bool scalar_lane = (j < 2);
    bool pA = (i0 == 0), pB = (i0 == 1);

    int estep = gridDim.x * 32;
    int e = blockIdx.x * 32 + wid * 4 + grp;

    float facc = 0.f;

    // ---- prologue: stage CUR (tile e) fully, NXT (tile e+estep) ev only ----
    float shC0, shC1, shC2, S1C;
    __half2 fr2C;
    uint4 hvC, hsC;
    float4 x4C;
    {
        int ec = (e < E) ? e : 0;
        float ex = __ldg(evec + 3 * ec + 0);
        float ey = __ldg(evec + 3 * ec + 1);
        float ez = __ldg(evec + 3 * ec + 2);
        int idx = __ldg(esrc + ec);
        float d2 = fmaf(ex, ex, fmaf(ey, ey, ez * ez));
        float ir = rsqrtf(d2);
        float r = d2 * ir;
        shC0 = ex * ir; shC1 = ey * ir; shC2 = ez * ir;
        S1C = shC0 + shC1 + shC2;
        float t = fminf(r * (NB / 3.0f), (float)NB);
        int irow = (int)t;
        fr2C = __float2half2_rn(t - (float)irow);
        const uint4* lbv = (const uint4*)g_LUTh + irow * 16 + j;
        hvC = __ldg(lbv);
        hsC = __ldg(lbv + 8);
        x4C = __ldg((const float4*)feat + (size_t)idx * 8 + j);
    }
    float exN, eyN, ezN;
    int idxN;
    {
        int en = e + estep;
        int ec = (en < E) ? en : 0;
        exN = __ldg(evec + 3 * ec + 0);
        eyN = __ldg(evec + 3 * ec + 1);
        ezN = __ldg(evec + 3 * ec + 2);
        idxN = __ldg(esrc + ec);
    }

    for (; e < E; e += estep) {
        // [1] ev/idx for tile e + 2*estep
        int e2 = e + 2 * estep;
        int ec2 = (e2 < E) ? e2 : 0;
        float exF = __ldg(evec + 3 * ec2 + 0);
        float eyF = __ldg(evec + 3 * ec2 + 1);
        float ezF = __ldg(evec + 3 * ec2 + 2);
        int idxF = __ldg(esrc + ec2);

        // [2] scalar chain + LUT/feat loads for tile e+estep (ev landed)
        float d2 = fmaf(exN, exN, fmaf(eyN, eyN, ezN * ezN));
        float ir = rsqrtf(d2);
        float r = d2 * ir;
        float shN0 = exN * ir, shN1 = eyN * ir, shN2 = ezN * ir;
        float S1N = shN0 + shN1 + shN2;
        float t = fminf(r * (NB / 3.0f), (float)NB);
        int irow = (int)t;
        __half2 fr2N = __float2half2_rn(t - (float)irow);
        const uint4* lbv = (const uint4*)g_LUTh + irow * 16 + j;
        uint4 hvN = __ldg(lbv);
        uint4 hsN = __ldg(lbv + 8);
        float4 x4N = __ldg((const float4*)feat + (size_t)idxN * 8 + j);

        // [3] consume tile e (LUT/feat landed one iteration ago)
        float ga = pA ? shC0 : (pB ? shC1 : shC2);
        float gb = pA ? shC1 : (pB ? shC2 : shC0);
        float gc = pA ? shC2 : (pB ? shC0 : shC1);
        float g0 = scalar_lane ? S1C : ga;
        float g1 = scalar_lane ? S1C : gb;
        float g2 = scalar_lane ? S1C : gc;
        float g3 = scalar_lane ? S1C : ga;
        {
            __half2 c2;
            float2 cf;
            c2 = __hfma2(fr2C, *(const __half2*)&hsC.x, *(const __half2*)&hvC.x);
            cf = __half22float2(c2);
            facc = fmaf(x4C.x, fmaf(cf.y, g0, cf.x), facc);
            c2 = __hfma2(fr2C, *(const __half2*)&hsC.y, *(const __half2*)&hvC.y);
            cf = __half22float2(c2);
            facc = fmaf(x4C.y, fmaf(cf.y, g1, cf.x), facc);
            c2 = __hfma2(fr2C, *(const __half2*)&hsC.z, *(const __half2*)&hvC.z);
            cf = __half22float2(c2);
            facc = fmaf(x4C.z, fmaf(cf.y, g2, cf.x), facc);
            c2 = __hfma2(fr2C, *(const __half2*)&hsC.w, *(const __half2*)&hvC.w);
            cf = __half22float2(c2);
            facc = fmaf(x4C.w, fmaf(cf.y, g3, cf.x), facc);
        }

        // rotate pipeline state
        shC0 = shN0; shC1 = shN1; shC2 = shN2; S1C = S1N; fr2C = fr2N;
        hvC = hvN; hsC = hsN; x4C = x4N;
        exN = exF; eyN = eyF; ezN = ezF; idxN = idxF;
    }

    finish_reduce(facc, out, tid, lane, wid);
}

// ---------------------------------------------------------------------------
// TAIL edge kernel (generic E): R15 1-deep pipeline with validity logic.
// ---------------------------------------------------------------------------
__global__ void __launch_bounds__(TPB)
edge_tail(const float* __restrict__ feat, const float* __restrict__ evec,
          const int* __restrict__ esrc, float* __restrict__ out, int E,
          int elimit) {
    int tid = threadIdx.x;
    int lane = tid & 31;
    int wid = tid >> 5;
    int grp = lane >> 3;
    int j = lane & 7;

    int i0 = (j + 1) % 3;
    bool scalar_lane = (j < 2);
    bool pA = (i0 == 0), pB = (i0 == 1);

    int estep = gridDim.x * 32;
    int e = blockIdx.x * 32 + wid * 4 + grp;

    float facc = 0.f;

    bool valid = e < E;
    int ec = valid ? e : 0;
    float ex = __ldg(evec + 3 * ec + 0);
    float ey = __ldg(evec + 3 * ec + 1);
    float ez = __ldg(evec + 3 * ec + 2);
    int idx = __ldg(esrc + ec);

    for (; e < elimit; e += estep) {
        float d2 = fmaf(ex, ex, fmaf(ey, ey, ez * ez));
        float inv_r = rsqrtf(d2);
        float r = d2 * inv_r;
        float sh0 = ex * inv_r, sh1 = ey * inv_r, sh2 = ez * inv_r;
        float S1 = sh0 + sh1 + sh2;
        float t = fminf(r * (NB / 3.0f), (float)NB);
        int irow = (int)t;
        float frac = t - (float)irow;

        const uint4* lbv = (const uint4*)g_LUTh + irow * 16 + j;
        uint4 hv = __ldg(lbv);
        uint4 hs = __ldg(lbv + 8);
        float4 x4 = __ldg((const float4*)feat + (size_t)idx * 8 + j);

        float ga = pA ? sh0 : (pB ? sh1 : sh2);
        float gb = pA ? sh1 : (pB ? sh2 : sh0);
        float gc = pA ? sh2 : (pB ? sh0 : sh1);
        float g0 = scalar_lane ? S1 : ga;
        float g1 = scalar_lane ? S1 : gb;
        float g2 = scalar_lane ? S1 : gc;
        float g3 = scalar_lane ? S1 : ga;
        bool curvalid = valid;

        int ne = e + estep;
        if (ne < elimit) {
            valid = ne < E;
            ec = valid ? ne : 0;
            ex = __ldg(evec + 3 * ec + 0);
            ey = __ldg(evec + 3 * ec + 1);
            ez = __ldg(evec + 3 * ec + 2);
            idx = __ldg(esrc + ec);
        }

        if (curvalid) {
            __half2 fr2 = __float2half2_rn(frac);
            __half2 c2;
            float2 cf;
            c2 = __hfma2(fr2, *(const __half2*)&hs.x, *(const __half2*)&hv.x);
            cf = __half22float2(c2);
            facc = fmaf(x4.x, fmaf(cf.y, g0, cf.x), facc);
            c2 = __hfma2(fr2, *(const __half2*)&hs.y, *(const __half2*)&hv.y);
            cf = __half22float2(c2);
            facc = fmaf(x4.y, fmaf(cf.y, g1, cf.x), facc);
            c2 = __hfma2(fr2, *(const __half2*)&hs.z, *(const __half2*)&hv.z);
            cf = __half22float2(c2);
            facc = fmaf(x4.z, fmaf(cf.y, g2, cf.x), facc);
            c2 = __hfma2(fr2, *(const __half2*)&hs.w, *(const __half2*)&hv.w);
            cf = __half22float2(c2);
            facc = fmaf(x4.w, fmaf(cf.y, g3, cf.x), facc);
        }
    }

    finish_reduce(facc, out, tid, lane, wid);
}

extern "C" void kernel_launch(void* const* d_in, const int* in_sizes, int n_in,
                              void* d_out, int out_size) {
    const float* feat = (const float*)d_in[0];  // (N, 32)
    const float* evec = (const float*)d_in[1];  // (E, 3)
    const float* W1   = (const float*)d_in[2];  // (10, 16)
    const float* W2   = (const float*)d_in[3];  // (16, 256)
    const int*   esrc = (const int*)d_in[4];    // (E,)
    // edge_dst / num_nodes drop out: segment_sum then total sum == sum over
    // edges; radial pipeline collapses to a 1-D (value, slope) fp16 LUT in r.
    int E = in_sizes[4];

    prep_kernel<<<(NROWS + 127) / 128, TPB>>>(W1, W2);
    if ((E & 31) == 0) {
        edge_fast<<<GRID_FAST, TPB>>>(feat, evec, esrc, (float*)d_out, E);
    } else {
        int elimit = ((E + 31) / 32) * 32;
        edge_tail<<<GRID_TAIL, TPB>>>(feat, evec, esrc, (float*)d_out, E,
                                      elimit);
    }
}